// round 1
// baseline (speedup 1.0000x reference)
#include <cuda_runtime.h>
#include <math.h>

#define N_NODES 50000
#define N_EDGES 800000
#define MULC 32
#define RADC 8
#define FCC 64

#define INV_SQRT_MUL 0.17677669529663687f   /* 1/sqrt(32) */
#define INV_SQRT_RAD 0.35355339059327373f   /* 1/sqrt(8)  */
#define INV_SQRT_FC  0.125f                 /* 1/sqrt(64) */
#define INV_SQRT_NN  0.25f                  /* 1/sqrt(16) */
#define INV_SQRT_2MUL 0.125f                /* 1/sqrt(64) */
#define INV_SQRT3_C 0.5773502691896258f
#define MIX_C 0.9238795325112867f           /* cos(pi/8) */
#define MIX_S 0.3826834323650898f           /* sin(pi/8) */

// ---------------- scratch (device globals; no allocation allowed) ----------
__device__ float g_f0[N_NODES * MULC];          // [n][c]
__device__ float g_f1[N_NODES * 3 * MULC];      // [n][i][c]
__device__ float g_self0[N_NODES * MULC];       // pre-scaled by cos(MIX)
__device__ float g_self1[N_NODES * 3 * MULC];   // pre-scaled by cos(MIX)
__device__ float g_n0[N_NODES * 2 * MULC];      // [n][ch64]
__device__ float g_n1[N_NODES * 3 * 2 * MULC];  // [n][i][ch64]

__device__ __forceinline__ float gelu_tanh(float x) {
    // matches jax.nn.gelu(approximate=True)
    float u = 0.7978845608028654f * (x + 0.044715f * x * x * x);
    return 0.5f * x * (1.0f + tanhf(u));
}

// ---------------- kernel 0: zero the accumulators --------------------------
__global__ void zero_kernel() {
    int i = blockIdx.x * blockDim.x + threadIdx.x;
    int stride = gridDim.x * blockDim.x;
    for (int k = i; k < N_NODES * 64; k += stride) g_n0[k] = 0.0f;
    for (int k = i; k < N_NODES * 192; k += stride) g_n1[k] = 0.0f;
}

// ---------------- kernel 1: node pre-transforms -----------------------------
// warp per node; lane = output channel v.
__global__ void node_pre_kernel(const float* __restrict__ node_s,
                                const float* __restrict__ node_v,
                                const float* __restrict__ Wf0,
                                const float* __restrict__ Ws0,
                                const float* __restrict__ Wf1,
                                const float* __restrict__ Ws1) {
    __shared__ float sWf0[1024], sWs0[1024], sWf1[1024], sWs1[1024];
    for (int i = threadIdx.x; i < 1024; i += blockDim.x) {
        sWf0[i] = Wf0[i] * INV_SQRT_MUL;
        sWs0[i] = Ws0[i] * (INV_SQRT_MUL * MIX_C);
        sWf1[i] = Wf1[i] * INV_SQRT_MUL;
        sWs1[i] = Ws1[i] * (INV_SQRT_MUL * MIX_C);
    }
    __syncthreads();

    int lane = threadIdx.x & 31;
    int warp = threadIdx.x >> 5;
    int n = blockIdx.x * (blockDim.x >> 5) + warp;
    if (n >= N_NODES) return;

    float sv  = node_s[n * 32 + lane];
    float vx  = node_v[n * 96 + lane * 3 + 0];
    float vy  = node_v[n * 96 + lane * 3 + 1];
    float vz  = node_v[n * 96 + lane * 3 + 2];

    float f0 = 0.f, s0 = 0.f;
    float f1x = 0.f, f1y = 0.f, f1z = 0.f;
    float s1x = 0.f, s1y = 0.f, s1z = 0.f;

    #pragma unroll 8
    for (int u = 0; u < 32; u++) {
        float su = __shfl_sync(0xffffffffu, sv, u);
        float ux = __shfl_sync(0xffffffffu, vx, u);
        float uy = __shfl_sync(0xffffffffu, vy, u);
        float uz = __shfl_sync(0xffffffffu, vz, u);
        float wf0 = sWf0[u * 32 + lane];
        float ws0 = sWs0[u * 32 + lane];
        float wf1 = sWf1[u * 32 + lane];
        float ws1 = sWs1[u * 32 + lane];
        f0 += su * wf0;  s0 += su * ws0;
        f1x += ux * wf1; f1y += uy * wf1; f1z += uz * wf1;
        s1x += ux * ws1; s1y += uy * ws1; s1z += uz * ws1;
    }

    g_f0[n * 32 + lane] = f0;
    g_self0[n * 32 + lane] = s0;
    g_f1[n * 96 + 0 * 32 + lane] = f1x;
    g_f1[n * 96 + 1 * 32 + lane] = f1y;
    g_f1[n * 96 + 2 * 32 + lane] = f1z;
    g_self1[n * 96 + 0 * 32 + lane] = s1x;
    g_self1[n * 96 + 1 * 32 + lane] = s1y;
    g_self1[n * 96 + 2 * 32 + lane] = s1z;
}

// ---------------- kernel 2: edge phase (dominant) ---------------------------
// warp per edge; lane = channel c. Dynamic smem: weights + per-warp h buffer.
#define EDGE_WARPS 8
#define EDGE_SMEM_FLOATS (512 + 4096 + 8192 + EDGE_WARPS * 64)

__global__ __launch_bounds__(EDGE_WARPS * 32)
void edge_kernel(const float* __restrict__ sh0,
                 const float* __restrict__ sh1,
                 const float* __restrict__ edge_scalar,
                 const int* __restrict__ edge_src,
                 const int* __restrict__ edge_dst,
                 const float* __restrict__ mlp_w0,
                 const float* __restrict__ mlp_w1,
                 const float* __restrict__ wp0,
                 const float* __restrict__ wp1,
                 const float* __restrict__ wp2,
                 const float* __restrict__ wp3) {
    extern __shared__ float sm[];
    float* sW0 = sm;             // 8*64
    float* sW1 = sm + 512;       // 64*64
    float* sWP = sm + 4608;      // [k][m][c] 64*4*32
    float* sH  = sm + 12800;     // per-warp 64

    for (int i = threadIdx.x; i < RADC * FCC; i += blockDim.x)
        sW0[i] = mlp_w0[i] * INV_SQRT_RAD;
    for (int i = threadIdx.x; i < FCC * FCC; i += blockDim.x)
        sW1[i] = mlp_w1[i] * INV_SQRT_FC;
    const float wpsc = INV_SQRT_FC * INV_SQRT_NN;
    for (int i = threadIdx.x; i < FCC * MULC; i += blockDim.x) {
        int k = i >> 5, c = i & 31;
        int b = k * 128 + c;
        sWP[b +  0] = wp0[i] * wpsc;
        sWP[b + 32] = wp1[i] * wpsc;
        sWP[b + 64] = wp2[i] * wpsc;
        sWP[b + 96] = wp3[i] * wpsc;
    }
    __syncthreads();

    int lane = threadIdx.x & 31;
    int warp = threadIdx.x >> 5;
    float* hbuf = sH + warp * 64;
    int gw = blockIdx.x * EDGE_WARPS + warp;
    int nw = gridDim.x * EDGE_WARPS;

    for (int e = gw; e < N_EDGES; e += nw) {
        int src = edge_src[e];
        int dst = edge_dst[e];

        // ---- radial MLP layer 0: (8 -> 64), gelu
        float es = edge_scalar[e * 8 + (lane & 7)];
        float a0 = 0.f, a1 = 0.f;
        #pragma unroll
        for (int r = 0; r < 8; r++) {
            float t = __shfl_sync(0xffffffffu, es, r);
            a0 += t * sW0[r * 64 + lane];
            a1 += t * sW0[r * 64 + 32 + lane];
        }
        __syncwarp();               // all prior hbuf readers done (iter >= 2)
        hbuf[lane]      = gelu_tanh(a0);
        hbuf[32 + lane] = gelu_tanh(a1);
        __syncwarp();

        // ---- layer 1: (64 -> 64), gelu
        a0 = 0.f; a1 = 0.f;
        #pragma unroll 16
        for (int k = 0; k < 64; k++) {
            float t = hbuf[k];
            a0 += t * sW1[k * 64 + lane];
            a1 += t * sW1[k * 64 + 32 + lane];
        }
        float h1a = gelu_tanh(a0);
        float h1b = gelu_tanh(a1);
        __syncwarp();
        hbuf[lane]      = h1a;
        hbuf[32 + lane] = h1b;
        __syncwarp();

        // ---- projections: w0..w3 (each 64 -> 32), inv_sqrt_nn folded in
        float w0 = 0.f, w1 = 0.f, w2 = 0.f, w3 = 0.f;
        #pragma unroll 16
        for (int k = 0; k < 64; k++) {
            float t = hbuf[k];
            const float* wp = sWP + k * 128 + lane;
            w0 += t * wp[0];
            w1 += t * wp[32];
            w2 += t * wp[64];
            w3 += t * wp[96];
        }

        // ---- gather source features (L2-resident)
        float e0  = g_f0[src * 32 + lane];
        float e1x = g_f1[src * 96 + 0 * 32 + lane];
        float e1y = g_f1[src * 96 + 1 * 32 + lane];
        float e1z = g_f1[src * 96 + 2 * 32 + lane];
        float s0v = __ldg(sh0 + e);
        float shx = __ldg(sh1 + e * 3 + 0);
        float shy = __ldg(sh1 + e * 3 + 1);
        float shz = __ldg(sh1 + e * 3 + 2);

        // ---- tensor products
        float p0 = w0 * e0 * s0v;
        float d  = e1x * shx + e1y * shy + e1z * shz;
        float p3 = w3 * d * INV_SQRT3_C;
        float w1e0 = w1 * e0;
        float w2s0 = w2 * s0v;

        // ---- scatter-add (coalesced 128B lines per warp op)
        float* n0p = g_n0 + dst * 64;
        float* n1p = g_n1 + dst * 192;
        atomicAdd(n0p + lane,        p0);
        atomicAdd(n0p + 32 + lane,   p3);
        atomicAdd(n1p + 0 * 64 + lane,      w1e0 * shx);
        atomicAdd(n1p + 0 * 64 + 32 + lane, w2s0 * e1x);
        atomicAdd(n1p + 1 * 64 + lane,      w1e0 * shy);
        atomicAdd(n1p + 1 * 64 + 32 + lane, w2s0 * e1y);
        atomicAdd(n1p + 2 * 64 + lane,      w1e0 * shz);
        atomicAdd(n1p + 2 * 64 + 32 + lane, w2s0 * e1z);
    }
}

// ---------------- kernel 3: output transform --------------------------------
// warp per node; lane = output channel v.
__global__ void out_kernel(const float* __restrict__ Wout0,
                           const float* __restrict__ Wout1,
                           float* __restrict__ out) {
    __shared__ float sW0[2048], sW1[2048];
    for (int i = threadIdx.x; i < 2048; i += blockDim.x) {
        sW0[i] = Wout0[i] * (MIX_S * INV_SQRT_2MUL);
        sW1[i] = Wout1[i] * (MIX_S * INV_SQRT_2MUL);
    }
    __syncthreads();

    int lane = threadIdx.x & 31;
    int warp = threadIdx.x >> 5;
    int n = blockIdx.x * (blockDim.x >> 5) + warp;
    if (n >= N_NODES) return;

    // scalar channel
    float n0a = g_n0[n * 64 + lane];
    float n0b = g_n0[n * 64 + 32 + lane];
    float acc0 = g_self0[n * 32 + lane];   // already cos(MIX)-scaled
    #pragma unroll 8
    for (int u = 0; u < 32; u++) {
        float ta = __shfl_sync(0xffffffffu, n0a, u);
        float tb = __shfl_sync(0xffffffffu, n0b, u);
        acc0 += ta * sW0[u * 32 + lane];
        acc0 += tb * sW0[(u + 32) * 32 + lane];
    }
    out[n * 128 + lane] = acc0;

    // vector channels
    #pragma unroll
    for (int i = 0; i < 3; i++) {
        float na = g_n1[n * 192 + i * 64 + lane];
        float nb = g_n1[n * 192 + i * 64 + 32 + lane];
        float acc = g_self1[n * 96 + i * 32 + lane];
        #pragma unroll 8
        for (int u = 0; u < 32; u++) {
            float ta = __shfl_sync(0xffffffffu, na, u);
            float tb = __shfl_sync(0xffffffffu, nb, u);
            acc += ta * sW1[u * 32 + lane];
            acc += tb * sW1[(u + 32) * 32 + lane];
        }
        out[n * 128 + 32 + lane * 3 + i] = acc;
    }
}

// ---------------- launch -----------------------------------------------------
extern "C" void kernel_launch(void* const* d_in, const int* in_sizes, int n_in,
                              void* d_out, int out_size) {
    const float* node_s      = (const float*)d_in[0];
    const float* node_v      = (const float*)d_in[1];
    const float* sh0         = (const float*)d_in[2];
    const float* sh1         = (const float*)d_in[3];
    const float* edge_scalar = (const float*)d_in[4];
    const int*   edge_src    = (const int*)d_in[5];
    const int*   edge_dst    = (const int*)d_in[6];
    const float* W_feat0     = (const float*)d_in[7];
    const float* W_self0     = (const float*)d_in[8];
    const float* W_feat1     = (const float*)d_in[9];
    const float* W_self1     = (const float*)d_in[10];
    const float* mlp_w0      = (const float*)d_in[11];
    const float* mlp_w1      = (const float*)d_in[12];
    const float* wp0         = (const float*)d_in[13];
    const float* wp1         = (const float*)d_in[14];
    const float* wp2         = (const float*)d_in[15];
    const float* wp3         = (const float*)d_in[16];
    const float* W_out0      = (const float*)d_in[17];
    const float* W_out1      = (const float*)d_in[18];
    float* out = (float*)d_out;

    zero_kernel<<<2048, 256>>>();
    node_pre_kernel<<<(N_NODES + 7) / 8, 256>>>(node_s, node_v,
                                                W_feat0, W_self0,
                                                W_feat1, W_self1);

    size_t edge_smem = EDGE_SMEM_FLOATS * sizeof(float);
    cudaFuncSetAttribute(edge_kernel,
                         cudaFuncAttributeMaxDynamicSharedMemorySize,
                         (int)edge_smem);
    edge_kernel<<<592, EDGE_WARPS * 32, edge_smem>>>(
        sh0, sh1, edge_scalar, edge_src, edge_dst,
        mlp_w0, mlp_w1, wp0, wp1, wp2, wp3);

    out_kernel<<<(N_NODES + 7) / 8, 256>>>(W_out0, W_out1, out);
}

// round 2
// speedup vs baseline: 2.3312x; 2.3312x over previous
#include <cuda_runtime.h>
#include <math.h>

#define N_NODES 50000
#define N_EDGES 800000
#define MULC 32
#define RADC 8
#define FCC 64
#define EB 8   /* edges per warp iteration */

#define INV_SQRT_MUL 0.17677669529663687f
#define INV_SQRT_RAD 0.35355339059327373f
#define INV_SQRT_FC  0.125f
#define INV_SQRT_NN  0.25f
#define INV_SQRT_2MUL 0.125f
#define INV_SQRT3_C 0.5773502691896258f
#define MIX_C 0.9238795325112867f
#define MIX_S 0.3826834323650898f

typedef unsigned long long u64;

// ---------------- f32x2 packed-math helpers (sm_103a) -----------------------
__device__ __forceinline__ u64 pack2(float lo, float hi) {
    u64 d; asm("mov.b64 %0, {%1, %2};" : "=l"(d) : "f"(lo), "f"(hi)); return d;
}
__device__ __forceinline__ float2 unpack2(u64 v) {
    float lo, hi; asm("mov.b64 {%0, %1}, %2;" : "=f"(lo), "=f"(hi) : "l"(v));
    return make_float2(lo, hi);
}
__device__ __forceinline__ u64 fma2(u64 a, u64 b, u64 c) {
    u64 d; asm("fma.rn.f32x2 %0, %1, %2, %3;" : "=l"(d) : "l"(a), "l"(b), "l"(c));
    return d;
}
__device__ __forceinline__ u64 ld2(const float2* p) {
    float2 v = *p;
    u64 d; asm("mov.b64 %0, {%1, %2};" : "=l"(d) : "f"(v.x), "f"(v.y)); return d;
}

// gelu(x) = 0.5 x (1 + tanh(u)) = x * sigmoid(2u),  u = 0.79788456(x + 0.044715 x^3)
__device__ __forceinline__ float gelu_fast(float x) {
    float x2 = x * x;
    float arg = x * (-1.5957691216057308f - 0.07135481627352344f * x2); // -2u
    float p = __expf(arg);
    return __fdividef(x, 1.0f + p);
}

// ---------------- scratch ----------------------------------------------------
__device__ __align__(16) float g_f0[N_NODES * MULC];
__device__ __align__(16) float g_f1[N_NODES * 3 * MULC];
__device__ __align__(16) float g_self0[N_NODES * MULC];
__device__ __align__(16) float g_self1[N_NODES * 3 * MULC];
__device__ __align__(16) float g_n0[N_NODES * 2 * MULC];
__device__ __align__(16) float g_n1[N_NODES * 3 * 2 * MULC];

// ---------------- kernel 0: zero ---------------------------------------------
__global__ void zero_kernel() {
    int i = blockIdx.x * blockDim.x + threadIdx.x;
    int stride = gridDim.x * blockDim.x;
    float4* p0 = (float4*)g_n0;
    float4* p1 = (float4*)g_n1;
    const float4 z = make_float4(0.f, 0.f, 0.f, 0.f);
    for (int k = i; k < N_NODES * 16; k += stride) p0[k] = z;
    for (int k = i; k < N_NODES * 48; k += stride) p1[k] = z;
}

// ---------------- kernel 1: node pre-transforms ------------------------------
__global__ void node_pre_kernel(const float* __restrict__ node_s,
                                const float* __restrict__ node_v,
                                const float* __restrict__ Wf0,
                                const float* __restrict__ Ws0,
                                const float* __restrict__ Wf1,
                                const float* __restrict__ Ws1) {
    __shared__ float sWf0[1024], sWs0[1024], sWf1[1024], sWs1[1024];
    for (int i = threadIdx.x; i < 1024; i += blockDim.x) {
        sWf0[i] = Wf0[i] * INV_SQRT_MUL;
        sWs0[i] = Ws0[i] * (INV_SQRT_MUL * MIX_C);
        sWf1[i] = Wf1[i] * INV_SQRT_MUL;
        sWs1[i] = Ws1[i] * (INV_SQRT_MUL * MIX_C);
    }
    __syncthreads();

    int lane = threadIdx.x & 31;
    int warp = threadIdx.x >> 5;
    int n = blockIdx.x * (blockDim.x >> 5) + warp;
    if (n >= N_NODES) return;

    float sv  = node_s[n * 32 + lane];
    float vx  = node_v[n * 96 + lane * 3 + 0];
    float vy  = node_v[n * 96 + lane * 3 + 1];
    float vz  = node_v[n * 96 + lane * 3 + 2];

    float f0 = 0.f, s0 = 0.f;
    float f1x = 0.f, f1y = 0.f, f1z = 0.f;
    float s1x = 0.f, s1y = 0.f, s1z = 0.f;

    #pragma unroll 8
    for (int u = 0; u < 32; u++) {
        float su = __shfl_sync(0xffffffffu, sv, u);
        float ux = __shfl_sync(0xffffffffu, vx, u);
        float uy = __shfl_sync(0xffffffffu, vy, u);
        float uz = __shfl_sync(0xffffffffu, vz, u);
        float wf0 = sWf0[u * 32 + lane];
        float ws0 = sWs0[u * 32 + lane];
        float wf1 = sWf1[u * 32 + lane];
        float ws1 = sWs1[u * 32 + lane];
        f0 += su * wf0;  s0 += su * ws0;
        f1x += ux * wf1; f1y += uy * wf1; f1z += uz * wf1;
        s1x += ux * ws1; s1y += uy * ws1; s1z += uz * ws1;
    }

    g_f0[n * 32 + lane] = f0;
    g_self0[n * 32 + lane] = s0;
    g_f1[n * 96 + 0 * 32 + lane] = f1x;
    g_f1[n * 96 + 1 * 32 + lane] = f1y;
    g_f1[n * 96 + 2 * 32 + lane] = f1z;
    g_self1[n * 96 + 0 * 32 + lane] = s1x;
    g_self1[n * 96 + 1 * 32 + lane] = s1y;
    g_self1[n * 96 + 2 * 32 + lane] = s1z;
}

// ---------------- kernel 2: edge phase ---------------------------------------
// warp processes EB=8 edges per iteration, lane = channel, f32x2 packs 2 edges.
#define EDGE_WARPS 8
#define EDGE_W_FLOATS (512 + 4096 + 8192)
#define EDGE_SMEM_BYTES (EDGE_W_FLOATS * 4 + EDGE_WARPS * 4 * 64 * 8)

__global__ __launch_bounds__(EDGE_WARPS * 32, 2)
void edge_kernel(const float* __restrict__ sh0,
                 const float* __restrict__ sh1,
                 const float* __restrict__ edge_scalar,
                 const int* __restrict__ edge_src,
                 const int* __restrict__ edge_dst,
                 const float* __restrict__ mlp_w0,
                 const float* __restrict__ mlp_w1,
                 const float* __restrict__ wp0,
                 const float* __restrict__ wp1,
                 const float* __restrict__ wp2,
                 const float* __restrict__ wp3) {
    extern __shared__ float sm[];
    float*  sW0 = sm;             // 8*64
    float*  sW1 = sm + 512;       // 64*64
    float*  sWP = sm + 4608;      // [k][m*32+c]
    float2* sH  = (float2*)(sm + EDGE_W_FLOATS);  // per-warp 4 pairs * 64

    for (int i = threadIdx.x; i < RADC * FCC; i += blockDim.x)
        sW0[i] = mlp_w0[i] * INV_SQRT_RAD;
    for (int i = threadIdx.x; i < FCC * FCC; i += blockDim.x)
        sW1[i] = mlp_w1[i] * INV_SQRT_FC;
    const float wpsc = INV_SQRT_FC * INV_SQRT_NN;
    for (int i = threadIdx.x; i < FCC * MULC; i += blockDim.x) {
        int k = i >> 5, c = i & 31;
        int b = k * 128 + c;
        sWP[b +  0] = wp0[i] * wpsc;
        sWP[b + 32] = wp1[i] * wpsc;
        sWP[b + 64] = wp2[i] * wpsc;
        sWP[b + 96] = wp3[i] * wpsc;
    }
    __syncthreads();

    const int lane = threadIdx.x & 31;
    const int warp = threadIdx.x >> 5;
    float2* hp = sH + warp * 256;     // hp[p*64 + k], p = edge pair 0..3

    int gw = blockIdx.x * EDGE_WARPS + warp;
    int nw = gridDim.x * EDGE_WARPS;
    const int NB = N_EDGES / EB;      // 100000, exact

    for (int b = gw; b < NB; b += nw) {
        const int eb = b * EB;

        // coalesced per-edge metadata
        float esA = edge_scalar[eb * 8 + lane];        // edges 0..3, r = lane&7
        float esB = edge_scalar[eb * 8 + 32 + lane];   // edges 4..7
        int srcv = 0, dstv = 0; float sh0v = 0.f, sh1v = 0.f;
        if (lane < 8) {
            srcv = edge_src[eb + lane];
            dstv = edge_dst[eb + lane];
            sh0v = sh0[eb + lane];
        }
        if (lane < 24) sh1v = sh1[eb * 3 + lane];

        // ---- layer 0: 8 -> 64 -------------------------------------------------
        u64 aL[4] = {0ull, 0ull, 0ull, 0ull};
        u64 aH[4] = {0ull, 0ull, 0ull, 0ull};
        #pragma unroll
        for (int r = 0; r < 8; r++) {
            float wl = sW0[r * 64 + lane];
            float wh = sW0[r * 64 + 32 + lane];
            u64 wl2 = pack2(wl, wl), wh2 = pack2(wh, wh);
            float t0 = __shfl_sync(0xffffffffu, esA, r);
            float t1 = __shfl_sync(0xffffffffu, esA, 8 + r);
            float t2 = __shfl_sync(0xffffffffu, esA, 16 + r);
            float t3 = __shfl_sync(0xffffffffu, esA, 24 + r);
            float t4 = __shfl_sync(0xffffffffu, esB, r);
            float t5 = __shfl_sync(0xffffffffu, esB, 8 + r);
            float t6 = __shfl_sync(0xffffffffu, esB, 16 + r);
            float t7 = __shfl_sync(0xffffffffu, esB, 24 + r);
            u64 e01 = pack2(t0, t1), e23 = pack2(t2, t3);
            u64 e45 = pack2(t4, t5), e67 = pack2(t6, t7);
            aL[0] = fma2(wl2, e01, aL[0]);  aH[0] = fma2(wh2, e01, aH[0]);
            aL[1] = fma2(wl2, e23, aL[1]);  aH[1] = fma2(wh2, e23, aH[1]);
            aL[2] = fma2(wl2, e45, aL[2]);  aH[2] = fma2(wh2, e45, aH[2]);
            aL[3] = fma2(wl2, e67, aL[3]);  aH[3] = fma2(wh2, e67, aH[3]);
        }
        __syncwarp();
        #pragma unroll
        for (int p = 0; p < 4; p++) {
            float2 lo = unpack2(aL[p]);
            float2 hi = unpack2(aH[p]);
            hp[p * 64 + lane]      = make_float2(gelu_fast(lo.x), gelu_fast(lo.y));
            hp[p * 64 + 32 + lane] = make_float2(gelu_fast(hi.x), gelu_fast(hi.y));
        }
        __syncwarp();

        // ---- layer 1: 64 -> 64 -----------------------------------------------
        u64 bL[4] = {0ull, 0ull, 0ull, 0ull};
        u64 bH[4] = {0ull, 0ull, 0ull, 0ull};
        #pragma unroll 8
        for (int k = 0; k < 64; k++) {
            float wl = sW1[k * 64 + lane];
            float wh = sW1[k * 64 + 32 + lane];
            u64 wl2 = pack2(wl, wl), wh2 = pack2(wh, wh);
            u64 h01 = ld2(hp + 0 * 64 + k);
            u64 h23 = ld2(hp + 1 * 64 + k);
            u64 h45 = ld2(hp + 2 * 64 + k);
            u64 h67 = ld2(hp + 3 * 64 + k);
            bL[0] = fma2(wl2, h01, bL[0]);  bH[0] = fma2(wh2, h01, bH[0]);
            bL[1] = fma2(wl2, h23, bL[1]);  bH[1] = fma2(wh2, h23, bH[1]);
            bL[2] = fma2(wl2, h45, bL[2]);  bH[2] = fma2(wh2, h45, bH[2]);
            bL[3] = fma2(wl2, h67, bL[3]);  bH[3] = fma2(wh2, h67, bH[3]);
        }
        __syncwarp();
        #pragma unroll
        for (int p = 0; p < 4; p++) {
            float2 lo = unpack2(bL[p]);
            float2 hi = unpack2(bH[p]);
            hp[p * 64 + lane]      = make_float2(gelu_fast(lo.x), gelu_fast(lo.y));
            hp[p * 64 + 32 + lane] = make_float2(gelu_fast(hi.x), gelu_fast(hi.y));
        }
        __syncwarp();

        // ---- projections: 64 -> 4x32 -------------------------------------------
        u64 c0[4] = {0ull, 0ull, 0ull, 0ull};
        u64 c1[4] = {0ull, 0ull, 0ull, 0ull};
        u64 c2[4] = {0ull, 0ull, 0ull, 0ull};
        u64 c3[4] = {0ull, 0ull, 0ull, 0ull};
        #pragma unroll 4
        for (int k = 0; k < 64; k++) {
            const float* wpk = sWP + k * 128 + lane;
            float w0s = wpk[0], w1s = wpk[32], w2s = wpk[64], w3s = wpk[96];
            u64 w0d = pack2(w0s, w0s), w1d = pack2(w1s, w1s);
            u64 w2d = pack2(w2s, w2s), w3d = pack2(w3s, w3s);
            u64 h01 = ld2(hp + 0 * 64 + k);
            u64 h23 = ld2(hp + 1 * 64 + k);
            u64 h45 = ld2(hp + 2 * 64 + k);
            u64 h67 = ld2(hp + 3 * 64 + k);
            c0[0] = fma2(w0d, h01, c0[0]);  c0[1] = fma2(w0d, h23, c0[1]);
            c0[2] = fma2(w0d, h45, c0[2]);  c0[3] = fma2(w0d, h67, c0[3]);
            c1[0] = fma2(w1d, h01, c1[0]);  c1[1] = fma2(w1d, h23, c1[1]);
            c1[2] = fma2(w1d, h45, c1[2]);  c1[3] = fma2(w1d, h67, c1[3]);
            c2[0] = fma2(w2d, h01, c2[0]);  c2[1] = fma2(w2d, h23, c2[1]);
            c2[2] = fma2(w2d, h45, c2[2]);  c2[3] = fma2(w2d, h67, c2[3]);
            c3[0] = fma2(w3d, h01, c3[0]);  c3[1] = fma2(w3d, h23, c3[1]);
            c3[2] = fma2(w3d, h45, c3[2]);  c3[3] = fma2(w3d, h67, c3[3]);
        }

        float w0f[8], w1f[8], w2f[8], w3f[8];
        #pragma unroll
        for (int p = 0; p < 4; p++) {
            float2 t;
            t = unpack2(c0[p]); w0f[2 * p] = t.x; w0f[2 * p + 1] = t.y;
            t = unpack2(c1[p]); w1f[2 * p] = t.x; w1f[2 * p + 1] = t.y;
            t = unpack2(c2[p]); w2f[2 * p] = t.x; w2f[2 * p + 1] = t.y;
            t = unpack2(c3[p]); w3f[2 * p] = t.x; w3f[2 * p + 1] = t.y;
        }

        // ---- tensor products + scatter-add ------------------------------------
        #pragma unroll
        for (int j = 0; j < 8; j++) {
            int src   = __shfl_sync(0xffffffffu, srcv, j);
            int dst   = __shfl_sync(0xffffffffu, dstv, j);
            float s0  = __shfl_sync(0xffffffffu, sh0v, j);
            float shx = __shfl_sync(0xffffffffu, sh1v, 3 * j + 0);
            float shy = __shfl_sync(0xffffffffu, sh1v, 3 * j + 1);
            float shz = __shfl_sync(0xffffffffu, sh1v, 3 * j + 2);

            float e0  = g_f0[src * 32 + lane];
            float e1x = g_f1[src * 96 + 0 * 32 + lane];
            float e1y = g_f1[src * 96 + 1 * 32 + lane];
            float e1z = g_f1[src * 96 + 2 * 32 + lane];

            float p0 = w0f[j] * e0 * s0;
            float d  = e1x * shx + e1y * shy + e1z * shz;
            float p3 = w3f[j] * d * INV_SQRT3_C;
            float w1e0 = w1f[j] * e0;
            float w2s0 = w2f[j] * s0;

            float* n0p = g_n0 + dst * 64;
            float* n1p = g_n1 + dst * 192;
            atomicAdd(n0p + lane,      p0);
            atomicAdd(n0p + 32 + lane, p3);
            atomicAdd(n1p + 0 * 64 + lane,      w1e0 * shx);
            atomicAdd(n1p + 0 * 64 + 32 + lane, w2s0 * e1x);
            atomicAdd(n1p + 1 * 64 + lane,      w1e0 * shy);
            atomicAdd(n1p + 1 * 64 + 32 + lane, w2s0 * e1y);
            atomicAdd(n1p + 2 * 64 + lane,      w1e0 * shz);
            atomicAdd(n1p + 2 * 64 + 32 + lane, w2s0 * e1z);
        }
    }
}

// ---------------- kernel 3: output transform ---------------------------------
__global__ void out_kernel(const float* __restrict__ Wout0,
                           const float* __restrict__ Wout1,
                           float* __restrict__ out) {
    __shared__ float sW0[2048], sW1[2048];
    for (int i = threadIdx.x; i < 2048; i += blockDim.x) {
        sW0[i] = Wout0[i] * (MIX_S * INV_SQRT_2MUL);
        sW1[i] = Wout1[i] * (MIX_S * INV_SQRT_2MUL);
    }
    __syncthreads();

    int lane = threadIdx.x & 31;
    int warp = threadIdx.x >> 5;
    int n = blockIdx.x * (blockDim.x >> 5) + warp;
    if (n >= N_NODES) return;

    float n0a = g_n0[n * 64 + lane];
    float n0b = g_n0[n * 64 + 32 + lane];
    float acc0 = g_self0[n * 32 + lane];
    #pragma unroll 8
    for (int u = 0; u < 32; u++) {
        float ta = __shfl_sync(0xffffffffu, n0a, u);
        float tb = __shfl_sync(0xffffffffu, n0b, u);
        acc0 += ta * sW0[u * 32 + lane];
        acc0 += tb * sW0[(u + 32) * 32 + lane];
    }
    out[n * 128 + lane] = acc0;

    #pragma unroll
    for (int i = 0; i < 3; i++) {
        float na = g_n1[n * 192 + i * 64 + lane];
        float nb = g_n1[n * 192 + i * 64 + 32 + lane];
        float acc = g_self1[n * 96 + i * 32 + lane];
        #pragma unroll 8
        for (int u = 0; u < 32; u++) {
            float ta = __shfl_sync(0xffffffffu, na, u);
            float tb = __shfl_sync(0xffffffffu, nb, u);
            acc += ta * sW1[u * 32 + lane];
            acc += tb * sW1[(u + 32) * 32 + lane];
        }
        out[n * 128 + 32 + lane * 3 + i] = acc;
    }
}

// ---------------- launch -------------------------------------------------------
extern "C" void kernel_launch(void* const* d_in, const int* in_sizes, int n_in,
                              void* d_out, int out_size) {
    const float* node_s      = (const float*)d_in[0];
    const float* node_v      = (const float*)d_in[1];
    const float* sh0         = (const float*)d_in[2];
    const float* sh1         = (const float*)d_in[3];
    const float* edge_scalar = (const float*)d_in[4];
    const int*   edge_src    = (const int*)d_in[5];
    const int*   edge_dst    = (const int*)d_in[6];
    const float* W_feat0     = (const float*)d_in[7];
    const float* W_self0     = (const float*)d_in[8];
    const float* W_feat1     = (const float*)d_in[9];
    const float* W_self1     = (const float*)d_in[10];
    const float* mlp_w0      = (const float*)d_in[11];
    const float* mlp_w1      = (const float*)d_in[12];
    const float* wp0         = (const float*)d_in[13];
    const float* wp1         = (const float*)d_in[14];
    const float* wp2         = (const float*)d_in[15];
    const float* wp3         = (const float*)d_in[16];
    const float* W_out0      = (const float*)d_in[17];
    const float* W_out1      = (const float*)d_in[18];
    float* out = (float*)d_out;

    zero_kernel<<<1024, 256>>>();
    node_pre_kernel<<<(N_NODES + 7) / 8, 256>>>(node_s, node_v,
                                                W_feat0, W_self0,
                                                W_feat1, W_self1);

    cudaFuncSetAttribute(edge_kernel,
                         cudaFuncAttributeMaxDynamicSharedMemorySize,
                         EDGE_SMEM_BYTES);
    edge_kernel<<<296, EDGE_WARPS * 32, EDGE_SMEM_BYTES>>>(
        sh0, sh1, edge_scalar, edge_src, edge_dst,
        mlp_w0, mlp_w1, wp0, wp1, wp2, wp3);

    out_kernel<<<(N_NODES + 7) / 8, 256>>>(W_out0, W_out1, out);
}

// round 3
// speedup vs baseline: 2.6379x; 1.1316x over previous
#include <cuda_runtime.h>
#include <math.h>

#define N_NODES 50000
#define N_EDGES 800000
#define MULC 32
#define RADC 8
#define FCC 64
#define EB 8   /* edges per warp iteration */

#define INV_SQRT_MUL 0.17677669529663687f
#define INV_SQRT_RAD 0.35355339059327373f
#define INV_SQRT_FC  0.125f
#define INV_SQRT_NN  0.25f
#define INV_SQRT_2MUL 0.125f
#define INV_SQRT3_C 0.5773502691896258f
#define MIX_C 0.9238795325112867f
#define MIX_S 0.3826834323650898f

typedef unsigned long long u64;

// ---------------- f32x2 packed-math helpers (sm_103a) -----------------------
__device__ __forceinline__ u64 pack2(float lo, float hi) {
    u64 d; asm("mov.b64 %0, {%1, %2};" : "=l"(d) : "f"(lo), "f"(hi)); return d;
}
__device__ __forceinline__ float2 unpack2(u64 v) {
    float lo, hi; asm("mov.b64 {%0, %1}, %2;" : "=f"(lo), "=f"(hi) : "l"(v));
    return make_float2(lo, hi);
}
__device__ __forceinline__ u64 fma2(u64 a, u64 b, u64 c) {
    u64 d; asm("fma.rn.f32x2 %0, %1, %2, %3;" : "=l"(d) : "l"(a), "l"(b), "l"(c));
    return d;
}
__device__ __forceinline__ u64 ld2(const float2* p) {
    float2 v = *p;
    u64 d; asm("mov.b64 %0, {%1, %2};" : "=l"(d) : "f"(v.x), "f"(v.y)); return d;
}

// gelu(x) = x * sigmoid(2u),  u = 0.79788456(x + 0.044715 x^3)
__device__ __forceinline__ float gelu_fast(float x) {
    float x2 = x * x;
    float arg = x * (-1.5957691216057308f - 0.07135481627352344f * x2); // -2u
    float p = __expf(arg);
    return __fdividef(x, 1.0f + p);
}

// ---------------- scratch ----------------------------------------------------
__device__ __align__(16) float g_f0[N_NODES * MULC];
__device__ __align__(16) float g_f1[N_NODES * 3 * MULC];
__device__ __align__(16) float g_self0[N_NODES * MULC];
__device__ __align__(16) float g_self1[N_NODES * 3 * MULC];
__device__ __align__(16) float g_n0[N_NODES * 2 * MULC];
__device__ __align__(16) float g_n1[N_NODES * 3 * 2 * MULC];

// ---------------- kernel 1: node pre-transforms + accumulator zeroing -------
#define PRE_BLOCKS 6250
#define ZERO_BLOCKS 1088
__global__ void node_pre_kernel(const float* __restrict__ node_s,
                                const float* __restrict__ node_v,
                                const float* __restrict__ Wf0,
                                const float* __restrict__ Ws0,
                                const float* __restrict__ Wf1,
                                const float* __restrict__ Ws1) {
    if (blockIdx.x >= PRE_BLOCKS) {
        // zeroing role
        int i = (blockIdx.x - PRE_BLOCKS) * blockDim.x + threadIdx.x;
        int stride = ZERO_BLOCKS * blockDim.x;
        float4* p0 = (float4*)g_n0;
        float4* p1 = (float4*)g_n1;
        const float4 z = make_float4(0.f, 0.f, 0.f, 0.f);
        for (int k = i; k < N_NODES * 16; k += stride) p0[k] = z;
        for (int k = i; k < N_NODES * 48; k += stride) p1[k] = z;
        return;
    }

    __shared__ float sWf0[1024], sWs0[1024], sWf1[1024], sWs1[1024];
    for (int i = threadIdx.x; i < 1024; i += blockDim.x) {
        sWf0[i] = Wf0[i] * INV_SQRT_MUL;
        sWs0[i] = Ws0[i] * (INV_SQRT_MUL * MIX_C);
        sWf1[i] = Wf1[i] * INV_SQRT_MUL;
        sWs1[i] = Ws1[i] * (INV_SQRT_MUL * MIX_C);
    }
    __syncthreads();

    int lane = threadIdx.x & 31;
    int warp = threadIdx.x >> 5;
    int n = blockIdx.x * (blockDim.x >> 5) + warp;
    if (n >= N_NODES) return;

    float sv  = node_s[n * 32 + lane];
    float vx  = node_v[n * 96 + lane * 3 + 0];
    float vy  = node_v[n * 96 + lane * 3 + 1];
    float vz  = node_v[n * 96 + lane * 3 + 2];

    float f0 = 0.f, s0 = 0.f;
    float f1x = 0.f, f1y = 0.f, f1z = 0.f;
    float s1x = 0.f, s1y = 0.f, s1z = 0.f;

    #pragma unroll 8
    for (int u = 0; u < 32; u++) {
        float su = __shfl_sync(0xffffffffu, sv, u);
        float ux = __shfl_sync(0xffffffffu, vx, u);
        float uy = __shfl_sync(0xffffffffu, vy, u);
        float uz = __shfl_sync(0xffffffffu, vz, u);
        float wf0 = sWf0[u * 32 + lane];
        float ws0 = sWs0[u * 32 + lane];
        float wf1 = sWf1[u * 32 + lane];
        float ws1 = sWs1[u * 32 + lane];
        f0 += su * wf0;  s0 += su * ws0;
        f1x += ux * wf1; f1y += uy * wf1; f1z += uz * wf1;
        s1x += ux * ws1; s1y += uy * ws1; s1z += uz * ws1;
    }

    g_f0[n * 32 + lane] = f0;
    g_self0[n * 32 + lane] = s0;
    g_f1[n * 96 + 0 * 32 + lane] = f1x;
    g_f1[n * 96 + 1 * 32 + lane] = f1y;
    g_f1[n * 96 + 2 * 32 + lane] = f1z;
    g_self1[n * 96 + 0 * 32 + lane] = s1x;
    g_self1[n * 96 + 1 * 32 + lane] = s1y;
    g_self1[n * 96 + 2 * 32 + lane] = s1z;
}

// ---------------- kernel 2: edge phase ---------------------------------------
// warp processes EB=8 edges per iteration, lane = channel, f32x2 packs 2 edges.
// smem layout (floats): sW0 512 | sW1p 4096 (float2) | sWP4 8192 (float4) | sH 4096
#define EDGE_WARPS 8
#define EDGE_SMEM_BYTES ((512 + 4096 + 8192 + 4096) * 4)

__global__ __launch_bounds__(EDGE_WARPS * 32, 2)
void edge_kernel(const float* __restrict__ sh0,
                 const float* __restrict__ sh1,
                 const float* __restrict__ edge_scalar,
                 const int* __restrict__ edge_src,
                 const int* __restrict__ edge_dst,
                 const float* __restrict__ mlp_w0,
                 const float* __restrict__ mlp_w1,
                 const float* __restrict__ wp0,
                 const float* __restrict__ wp1,
                 const float* __restrict__ wp2,
                 const float* __restrict__ wp3) {
    extern __shared__ float sm[];
    float*  sW0  = sm;                               // 8*64
    float2* sW1p = (float2*)(sm + 512);              // [k][c] -> (W[k][c], W[k][c+32])
    float4* sWP4 = (float4*)(sm + 512 + 4096);       // [k][c] -> (wp0,wp1,wp2,wp3)
    float2* sH   = (float2*)(sm + 512 + 4096 + 8192);// per-warp 4 pairs * 64

    for (int i = threadIdx.x; i < RADC * FCC; i += blockDim.x)
        sW0[i] = mlp_w0[i] * INV_SQRT_RAD;
    for (int i = threadIdx.x; i < 2048; i += blockDim.x) {
        int k = i >> 5, c = i & 31;
        sW1p[i] = make_float2(mlp_w1[k * 64 + c] * INV_SQRT_FC,
                              mlp_w1[k * 64 + 32 + c] * INV_SQRT_FC);
    }
    const float wpsc = INV_SQRT_FC * INV_SQRT_NN;
    for (int i = threadIdx.x; i < FCC * MULC; i += blockDim.x) {
        sWP4[i] = make_float4(wp0[i] * wpsc, wp1[i] * wpsc,
                              wp2[i] * wpsc, wp3[i] * wpsc);
    }
    __syncthreads();

    const int lane = threadIdx.x & 31;
    const int warp = threadIdx.x >> 5;
    float2* hp = sH + warp * 256;     // hp[p*64 + k], p = edge pair 0..3

    int gw = blockIdx.x * EDGE_WARPS + warp;
    int nw = gridDim.x * EDGE_WARPS;
    const int NB = N_EDGES / EB;      // 100000, exact

    for (int b = gw; b < NB; b += nw) {
        const int eb = b * EB;

        float esA = edge_scalar[eb * 8 + lane];
        float esB = edge_scalar[eb * 8 + 32 + lane];
        int srcv = 0, dstv = 0; float sh0v = 0.f, sh1v = 0.f;
        if (lane < 8) {
            srcv = edge_src[eb + lane];
            dstv = edge_dst[eb + lane];
            sh0v = sh0[eb + lane];
        }
        if (lane < 24) sh1v = sh1[eb * 3 + lane];

        // ---- layer 0: 8 -> 64 ------------------------------------------------
        u64 aL[4] = {0ull, 0ull, 0ull, 0ull};
        u64 aH[4] = {0ull, 0ull, 0ull, 0ull};
        #pragma unroll
        for (int r = 0; r < 8; r++) {
            float wl = sW0[r * 64 + lane];
            float wh = sW0[r * 64 + 32 + lane];
            u64 wl2 = pack2(wl, wl), wh2 = pack2(wh, wh);
            float t0 = __shfl_sync(0xffffffffu, esA, r);
            float t1 = __shfl_sync(0xffffffffu, esA, 8 + r);
            float t2 = __shfl_sync(0xffffffffu, esA, 16 + r);
            float t3 = __shfl_sync(0xffffffffu, esA, 24 + r);
            float t4 = __shfl_sync(0xffffffffu, esB, r);
            float t5 = __shfl_sync(0xffffffffu, esB, 8 + r);
            float t6 = __shfl_sync(0xffffffffu, esB, 16 + r);
            float t7 = __shfl_sync(0xffffffffu, esB, 24 + r);
            u64 e01 = pack2(t0, t1), e23 = pack2(t2, t3);
            u64 e45 = pack2(t4, t5), e67 = pack2(t6, t7);
            aL[0] = fma2(wl2, e01, aL[0]);  aH[0] = fma2(wh2, e01, aH[0]);
            aL[1] = fma2(wl2, e23, aL[1]);  aH[1] = fma2(wh2, e23, aH[1]);
            aL[2] = fma2(wl2, e45, aL[2]);  aH[2] = fma2(wh2, e45, aH[2]);
            aL[3] = fma2(wl2, e67, aL[3]);  aH[3] = fma2(wh2, e67, aH[3]);
        }
        __syncwarp();
        #pragma unroll
        for (int p = 0; p < 4; p++) {
            float2 lo = unpack2(aL[p]);
            float2 hi = unpack2(aH[p]);
            hp[p * 64 + lane]      = make_float2(gelu_fast(lo.x), gelu_fast(lo.y));
            hp[p * 64 + 32 + lane] = make_float2(gelu_fast(hi.x), gelu_fast(hi.y));
        }
        __syncwarp();

        // ---- layer 1: 64 -> 64 -----------------------------------------------
        u64 bL[4] = {0ull, 0ull, 0ull, 0ull};
        u64 bH[4] = {0ull, 0ull, 0ull, 0ull};
        #pragma unroll 8
        for (int k = 0; k < 64; k++) {
            float2 w = sW1p[k * 32 + lane];
            u64 wl2 = pack2(w.x, w.x), wh2 = pack2(w.y, w.y);
            u64 h01 = ld2(hp + 0 * 64 + k);
            u64 h23 = ld2(hp + 1 * 64 + k);
            u64 h45 = ld2(hp + 2 * 64 + k);
            u64 h67 = ld2(hp + 3 * 64 + k);
            bL[0] = fma2(wl2, h01, bL[0]);  bH[0] = fma2(wh2, h01, bH[0]);
            bL[1] = fma2(wl2, h23, bL[1]);  bH[1] = fma2(wh2, h23, bH[1]);
            bL[2] = fma2(wl2, h45, bL[2]);  bH[2] = fma2(wh2, h45, bH[2]);
            bL[3] = fma2(wl2, h67, bL[3]);  bH[3] = fma2(wh2, h67, bH[3]);
        }
        __syncwarp();
        #pragma unroll
        for (int p = 0; p < 4; p++) {
            float2 lo = unpack2(bL[p]);
            float2 hi = unpack2(bH[p]);
            hp[p * 64 + lane]      = make_float2(gelu_fast(lo.x), gelu_fast(lo.y));
            hp[p * 64 + 32 + lane] = make_float2(gelu_fast(hi.x), gelu_fast(hi.y));
        }
        __syncwarp();

        // ---- projections: 64 -> 4x32 -------------------------------------------
        u64 c0[4] = {0ull, 0ull, 0ull, 0ull};
        u64 c1[4] = {0ull, 0ull, 0ull, 0ull};
        u64 c2[4] = {0ull, 0ull, 0ull, 0ull};
        u64 c3[4] = {0ull, 0ull, 0ull, 0ull};
        #pragma unroll 4
        for (int k = 0; k < 64; k++) {
            float4 w4 = sWP4[k * 32 + lane];
            u64 w0d = pack2(w4.x, w4.x), w1d = pack2(w4.y, w4.y);
            u64 w2d = pack2(w4.z, w4.z), w3d = pack2(w4.w, w4.w);
            u64 h01 = ld2(hp + 0 * 64 + k);
            u64 h23 = ld2(hp + 1 * 64 + k);
            u64 h45 = ld2(hp + 2 * 64 + k);
            u64 h67 = ld2(hp + 3 * 64 + k);
            c0[0] = fma2(w0d, h01, c0[0]);  c0[1] = fma2(w0d, h23, c0[1]);
            c0[2] = fma2(w0d, h45, c0[2]);  c0[3] = fma2(w0d, h67, c0[3]);
            c1[0] = fma2(w1d, h01, c1[0]);  c1[1] = fma2(w1d, h23, c1[1]);
            c1[2] = fma2(w1d, h45, c1[2]);  c1[3] = fma2(w1d, h67, c1[3]);
            c2[0] = fma2(w2d, h01, c2[0]);  c2[1] = fma2(w2d, h23, c2[1]);
            c2[2] = fma2(w2d, h45, c2[2]);  c2[3] = fma2(w2d, h67, c2[3]);
            c3[0] = fma2(w3d, h01, c3[0]);  c3[1] = fma2(w3d, h23, c3[1]);
            c3[2] = fma2(w3d, h45, c3[2]);  c3[3] = fma2(w3d, h67, c3[3]);
        }

        float w0f[8], w1f[8], w2f[8], w3f[8];
        #pragma unroll
        for (int p = 0; p < 4; p++) {
            float2 t;
            t = unpack2(c0[p]); w0f[2 * p] = t.x; w0f[2 * p + 1] = t.y;
            t = unpack2(c1[p]); w1f[2 * p] = t.x; w1f[2 * p + 1] = t.y;
            t = unpack2(c2[p]); w2f[2 * p] = t.x; w2f[2 * p + 1] = t.y;
            t = unpack2(c3[p]); w3f[2 * p] = t.x; w3f[2 * p + 1] = t.y;
        }

        // ---- tensor products + scatter-add ------------------------------------
        #pragma unroll
        for (int j = 0; j < 8; j++) {
            int src   = __shfl_sync(0xffffffffu, srcv, j);
            int dst   = __shfl_sync(0xffffffffu, dstv, j);
            float s0  = __shfl_sync(0xffffffffu, sh0v, j);
            float shx = __shfl_sync(0xffffffffu, sh1v, 3 * j + 0);
            float shy = __shfl_sync(0xffffffffu, sh1v, 3 * j + 1);
            float shz = __shfl_sync(0xffffffffu, sh1v, 3 * j + 2);

            const float* f0p = g_f0 + src * 32;
            const float* f1p = g_f1 + src * 96;
            float e0  = f0p[lane];
            float e1x = f1p[lane];
            float e1y = f1p[32 + lane];
            float e1z = f1p[64 + lane];

            float p0 = w0f[j] * e0 * s0;
            float d  = e1x * shx + e1y * shy + e1z * shz;
            float p3 = w3f[j] * d * INV_SQRT3_C;
            float w1e0 = w1f[j] * e0;
            float w2s0 = w2f[j] * s0;

            float* n0p = g_n0 + dst * 64;
            float* n1p = g_n1 + dst * 192;
            atomicAdd(n0p + lane,      p0);
            atomicAdd(n0p + 32 + lane, p3);
            atomicAdd(n1p + 0 * 64 + lane,      w1e0 * shx);
            atomicAdd(n1p + 0 * 64 + 32 + lane, w2s0 * e1x);
            atomicAdd(n1p + 1 * 64 + lane,      w1e0 * shy);
            atomicAdd(n1p + 1 * 64 + 32 + lane, w2s0 * e1y);
            atomicAdd(n1p + 2 * 64 + lane,      w1e0 * shz);
            atomicAdd(n1p + 2 * 64 + 32 + lane, w2s0 * e1z);
        }
    }
}

// ---------------- kernel 3: output transform ---------------------------------
// 4 nodes per warp; lane = output channel; f32x2 packs k-pairs (no dup packs).
#define OUT_WARPS 8
// smem: sW0t 1024 float2 | sW1t 1024 float2 | per-warp stage 4*(64+192) floats
#define OUT_SMEM_BYTES ((2048 + 2048) * 4 + OUT_WARPS * 1024 * 4)

__global__ __launch_bounds__(OUT_WARPS * 32, 2)
void out_kernel(const float* __restrict__ Wout0,
                const float* __restrict__ Wout1,
                float* __restrict__ out) {
    extern __shared__ float sm[];
    float2* sW0t = (float2*)sm;            // [kp][c] = (W0[2kp][c], W0[2kp+1][c])
    float2* sW1t = (float2*)(sm + 2048);
    float*  sStg = sm + 4096;              // per-warp: 4 nodes * 256 floats

    const float osc = MIX_S * INV_SQRT_2MUL;
    for (int i = threadIdx.x; i < 1024; i += blockDim.x) {
        int kp = i >> 5, c = i & 31;
        sW0t[i] = make_float2(Wout0[(2 * kp) * 32 + c] * osc,
                              Wout0[(2 * kp + 1) * 32 + c] * osc);
        sW1t[i] = make_float2(Wout1[(2 * kp) * 32 + c] * osc,
                              Wout1[(2 * kp + 1) * 32 + c] * osc);
    }
    __syncthreads();

    const int lane = threadIdx.x & 31;
    const int warp = threadIdx.x >> 5;
    float* stg = sStg + warp * 1024;   // [m][256]: n0 at +0 (64), n1 at +64 (192)

    int gw = blockIdx.x * OUT_WARPS + warp;
    int nw = gridDim.x * OUT_WARPS;
    const int NG = N_NODES / 4;        // 12500, exact

    for (int g = gw; g < NG; g += nw) {
        const int nb = g * 4;

        // stage 4 nodes' n0 + n1 into smem (natural layout)
        #pragma unroll
        for (int m = 0; m < 4; m++) {
            const float* n0s = g_n0 + (nb + m) * 64;
            const float* n1s = g_n1 + (nb + m) * 192;
            float* s = stg + m * 256;
            s[lane]      = n0s[lane];
            s[32 + lane] = n0s[32 + lane];
            #pragma unroll
            for (int i = 0; i < 3; i++) {
                s[64 + i * 64 + lane]      = n1s[i * 64 + lane];
                s[64 + i * 64 + 32 + lane] = n1s[i * 64 + 32 + lane];
            }
        }
        __syncwarp();

        // scalar outputs
        u64 accS[4];
        #pragma unroll
        for (int m = 0; m < 4; m++)
            accS[m] = pack2(g_self0[(nb + m) * 32 + lane], 0.0f);
        #pragma unroll 8
        for (int kp = 0; kp < 32; kp++) {
            u64 w2 = ld2(sW0t + kp * 32 + lane);
            #pragma unroll
            for (int m = 0; m < 4; m++) {
                u64 h2 = ld2((const float2*)(stg + m * 256 + 2 * kp));
                accS[m] = fma2(w2, h2, accS[m]);
            }
        }
        #pragma unroll
        for (int m = 0; m < 4; m++) {
            float2 t = unpack2(accS[m]);
            out[(nb + m) * 128 + lane] = t.x + t.y;
        }

        // vector outputs
        u64 accV[4][3];
        #pragma unroll
        for (int m = 0; m < 4; m++)
            #pragma unroll
            for (int i = 0; i < 3; i++)
                accV[m][i] = pack2(g_self1[(nb + m) * 96 + i * 32 + lane], 0.0f);
        #pragma unroll 4
        for (int kp = 0; kp < 32; kp++) {
            u64 w2 = ld2(sW1t + kp * 32 + lane);
            #pragma unroll
            for (int m = 0; m < 4; m++) {
                const float* s = stg + m * 256 + 64;
                u64 h0 = ld2((const float2*)(s + 0 * 64 + 2 * kp));
                u64 h1 = ld2((const float2*)(s + 1 * 64 + 2 * kp));
                u64 h2v = ld2((const float2*)(s + 2 * 64 + 2 * kp));
                accV[m][0] = fma2(w2, h0, accV[m][0]);
                accV[m][1] = fma2(w2, h1, accV[m][1]);
                accV[m][2] = fma2(w2, h2v, accV[m][2]);
            }
        }
        #pragma unroll
        for (int m = 0; m < 4; m++) {
            #pragma unroll
            for (int i = 0; i < 3; i++) {
                float2 t = unpack2(accV[m][i]);
                out[(nb + m) * 128 + 32 + lane * 3 + i] = t.x + t.y;
            }
        }
    }
}

// ---------------- launch -------------------------------------------------------
extern "C" void kernel_launch(void* const* d_in, const int* in_sizes, int n_in,
                              void* d_out, int out_size) {
    const float* node_s      = (const float*)d_in[0];
    const float* node_v      = (const float*)d_in[1];
    const float* sh0         = (const float*)d_in[2];
    const float* sh1         = (const float*)d_in[3];
    const float* edge_scalar = (const float*)d_in[4];
    const int*   edge_src    = (const int*)d_in[5];
    const int*   edge_dst    = (const int*)d_in[6];
    const float* W_feat0     = (const float*)d_in[7];
    const float* W_self0     = (const float*)d_in[8];
    const float* W_feat1     = (const float*)d_in[9];
    const float* W_self1     = (const float*)d_in[10];
    const float* mlp_w0      = (const float*)d_in[11];
    const float* mlp_w1      = (const float*)d_in[12];
    const float* wp0         = (const float*)d_in[13];
    const float* wp1         = (const float*)d_in[14];
    const float* wp2         = (const float*)d_in[15];
    const float* wp3         = (const float*)d_in[16];
    const float* W_out0      = (const float*)d_in[17];
    const float* W_out1      = (const float*)d_in[18];
    float* out = (float*)d_out;

    node_pre_kernel<<<PRE_BLOCKS + ZERO_BLOCKS, 256>>>(node_s, node_v,
                                                       W_feat0, W_self0,
                                                       W_feat1, W_self1);

    cudaFuncSetAttribute(edge_kernel,
                         cudaFuncAttributeMaxDynamicSharedMemorySize,
                         EDGE_SMEM_BYTES);
    edge_kernel<<<296, EDGE_WARPS * 32, EDGE_SMEM_BYTES>>>(
        sh0, sh1, edge_scalar, edge_src, edge_dst,
        mlp_w0, mlp_w1, wp0, wp1, wp2, wp3);

    cudaFuncSetAttribute(out_kernel,
                         cudaFuncAttributeMaxDynamicSharedMemorySize,
                         OUT_SMEM_BYTES);
    out_kernel<<<391, OUT_WARPS * 32, OUT_SMEM_BYTES>>>(W_out0, W_out1, out);
}